// round 1
// baseline (speedup 1.0000x reference)
#include <cuda_runtime.h>

// Problem constants
#define S_DIM 8192
#define E_DIM 512
#define B_DIM 8
#define SE_DIM (S_DIM * E_DIM)          // 4194304 = 2^22
#define M_TOTAL (B_DIM * S_DIM)         // 65536
#define K_DIM 512
#define N_DIM 512

// 128 MB permuted-A scratch (static __device__ allocation — allowed by harness rules)
__device__ float g_A[(size_t)B_DIM * SE_DIM];

// ---------------------------------------------------------------------------
// Fast cos via Cody-Waite range reduction + minimax polys (all FMA-pipe,
// no MUFU — MUFU throughput would cost ~230us for 33.5M elements).
// Accuracy ~1-2 ulp for |t| < ~1e3, far beyond the inputs here (|x+theta|<~10).
// ---------------------------------------------------------------------------
__device__ __forceinline__ float fast_cos(float t) {
    float q = rintf(t * 0.63661977236758134f);       // t * 2/pi
    int iq = (int)q;
    // pi/2 = PI_HI - 4.37113900e-8 (fp32 split)
    float r = fmaf(q, -1.57079637050628662109375f, t);
    r = fmaf(q, 4.37113900018624283e-8f, r);
    float z = r * r;
    // sin(r) on [-pi/4, pi/4]
    float sp = fmaf(z, -1.9515295891e-4f, 8.3321608736e-3f);
    sp = fmaf(z, sp, -1.6666654611e-1f);
    float sinr = fmaf(r * z, sp, r);
    // cos(r) on [-pi/4, pi/4]
    float cp = fmaf(z, 2.443315711809948e-5f, -1.388731625493765e-3f);
    cp = fmaf(z, cp, 4.166664568298827e-2f);
    cp = fmaf(z, cp, -0.5f);
    float cosr = fmaf(z, cp, 1.0f);
    // quadrant select: cos(r + q*pi/2)
    float res = (iq & 1) ? sinr : cosr;
    if ((iq + 1) & 2) res = -res;
    return res;
}

// ---------------------------------------------------------------------------
// Stage 1: A_perm[b, h*S*8 + s*8 + k] = cos(x[b, s, h*8+k] + theta[k])
// Coalesced float4 reads of x; 16B (sector-aligned) permuted writes.
// ---------------------------------------------------------------------------
__global__ __launch_bounds__(256) void stage1_kernel(const float* __restrict__ x,
                                                     const float* __restrict__ theta) {
    int gid = blockIdx.x * blockDim.x + threadIdx.x;
    int e0 = gid << 2;                      // element index (float4 granular), < 2^25
    int b   = e0 >> 22;                     // / SE_DIM
    int rem = e0 & (SE_DIM - 1);
    int s   = rem >> 9;                     // / E_DIM
    int e   = rem & (E_DIM - 1);
    int h   = e >> 3;                       // head
    int kk  = e & 7;                        // wire base (0 or 4 for aligned float4)

    float4 xv = *(const float4*)(x + e0);
    float t0 = __ldg(theta + kk + 0);
    float t1 = __ldg(theta + kk + 1);
    float t2 = __ldg(theta + kk + 2);
    float t3 = __ldg(theta + kk + 3);

    float4 o;
    o.x = fast_cos(xv.x + t0);
    o.y = fast_cos(xv.y + t1);
    o.z = fast_cos(xv.z + t2);
    o.w = fast_cos(xv.w + t3);

    size_t off = ((size_t)b << 22) + (size_t)h * (S_DIM * 8) + (size_t)s * 8 + kk;
    *(float4*)(g_A + off) = o;
}

// ---------------------------------------------------------------------------
// Stage 2: y[m, n] = sum_k A[m, k] * W[n, k]
// M=65536, N=512, K=512. Classic fp32 SMEM-tiled GEMM:
// block tile 128x128, k-slab 8, 256 threads, 8x8 microtile per thread.
// ---------------------------------------------------------------------------
__global__ __launch_bounds__(256) void gemm_kernel(const float* __restrict__ W,
                                                   float* __restrict__ C) {
    __shared__ float As[8][128];
    __shared__ float Bs[8][128];

    int tid = threadIdx.x;
    int m0 = blockIdx.y << 7;
    int n0 = blockIdx.x << 7;
    int tx = tid & 15;          // n micro-tile index
    int ty = tid >> 4;          // m micro-tile index

    // Global load mapping: 256 threads cover 128 rows x 8 cols as one float4 each
    int lrow = tid >> 1;
    int lcol = (tid & 1) << 2;
    const float* Aptr = g_A + (size_t)(m0 + lrow) * K_DIM + lcol;
    const float* Wptr = W   + (size_t)(n0 + lrow) * K_DIM + lcol;

    float acc[8][8];
#pragma unroll
    for (int i = 0; i < 8; i++)
#pragma unroll
        for (int j = 0; j < 8; j++) acc[i][j] = 0.0f;

    for (int kt = 0; kt < K_DIM; kt += 8) {
        float4 av = *(const float4*)(Aptr + kt);
        float4 wv = *(const float4*)(Wptr + kt);
        __syncthreads();   // previous iteration's reads complete
        As[lcol + 0][lrow] = av.x;
        As[lcol + 1][lrow] = av.y;
        As[lcol + 2][lrow] = av.z;
        As[lcol + 3][lrow] = av.w;
        Bs[lcol + 0][lrow] = wv.x;
        Bs[lcol + 1][lrow] = wv.y;
        Bs[lcol + 2][lrow] = wv.z;
        Bs[lcol + 3][lrow] = wv.w;
        __syncthreads();

#pragma unroll
        for (int kk = 0; kk < 8; kk++) {
            float4 a0 = *(const float4*)&As[kk][(ty << 3)];
            float4 a1 = *(const float4*)&As[kk][(ty << 3) + 4];
            float4 b0 = *(const float4*)&Bs[kk][(tx << 3)];
            float4 b1 = *(const float4*)&Bs[kk][(tx << 3) + 4];
            float a[8] = {a0.x, a0.y, a0.z, a0.w, a1.x, a1.y, a1.z, a1.w};
            float bb[8] = {b0.x, b0.y, b0.z, b0.w, b1.x, b1.y, b1.z, b1.w};
#pragma unroll
            for (int i = 0; i < 8; i++)
#pragma unroll
                for (int j = 0; j < 8; j++)
                    acc[i][j] = fmaf(a[i], bb[j], acc[i][j]);
        }
    }

    // Epilogue: float4 stores
#pragma unroll
    for (int i = 0; i < 8; i++) {
        size_t row = (size_t)(m0 + (ty << 3) + i);
        float4 s0 = make_float4(acc[i][0], acc[i][1], acc[i][2], acc[i][3]);
        float4 s1 = make_float4(acc[i][4], acc[i][5], acc[i][6], acc[i][7]);
        *(float4*)(C + row * N_DIM + n0 + (tx << 3))     = s0;
        *(float4*)(C + row * N_DIM + n0 + (tx << 3) + 4) = s1;
    }
}

extern "C" void kernel_launch(void* const* d_in, const int* in_sizes, int n_in,
                              void* d_out, int out_size) {
    const float* x     = (const float*)d_in[0];
    const float* theta = (const float*)d_in[1];
    const float* W     = (const float*)d_in[2];
    float* y = (float*)d_out;

    // Stage 1: 33554432 elems / 4 per thread / 256 per block = 32768 blocks
    stage1_kernel<<<32768, 256>>>(x, theta);

    // Stage 2: grid (N/128, M/128) = (4, 512)
    gemm_kernel<<<dim3(N_DIM / 128, M_TOTAL / 128), 256>>>(W, y);
}

// round 3
// speedup vs baseline: 5.0811x; 5.0811x over previous
#include <cuda_runtime.h>
#include <cstdint>

#define S_DIM 8192
#define E_DIM 512
#define B_DIM 8
#define SE_DIM (S_DIM * E_DIM)          // 4194304
#define M_TOTAL (B_DIM * S_DIM)         // 65536
#define K_DIM 512
#define N_DIM 512

// tcgen05 is only legal in the arch-specific ("a") compile pass.
#if defined(__CUDA_ARCH_FEAT_SM103_ALL) || defined(__CUDA_ARCH_FEAT_SM100_ALL) || \
    defined(__CUDA_ARCH_FEAT_SM101_ALL) || defined(__CUDA_ARCH_FEAT_SM110_ALL)
#define HAS_TCGEN05 1
#else
#define HAS_TCGEN05 0
#endif

// Scratch: permuted+cos'd+tf32-rounded A (128MB), tf32-rounded W (1MB)
__device__ float g_A[(size_t)M_TOTAL * K_DIM];
__device__ float g_W32[(size_t)N_DIM * K_DIM];

// ---------------------------------------------------------------------------
// helpers
// ---------------------------------------------------------------------------
__device__ __forceinline__ float to_tf32(float v) {
    float r;
    asm("cvt.rna.tf32.f32 %0, %1;" : "=f"(r) : "f"(v));
    return r;
}

__device__ __forceinline__ float fast_cos(float t) {
    float q = rintf(t * 0.63661977236758134f);
    int iq = (int)q;
    float r = fmaf(q, -1.57079637050628662109375f, t);
    r = fmaf(q, 4.37113900018624283e-8f, r);
    float z = r * r;
    float sp = fmaf(z, -1.9515295891e-4f, 8.3321608736e-3f);
    sp = fmaf(z, sp, -1.6666654611e-1f);
    float sinr = fmaf(r * z, sp, r);
    float cp = fmaf(z, 2.443315711809948e-5f, -1.388731625493765e-3f);
    cp = fmaf(z, cp, 4.166664568298827e-2f);
    cp = fmaf(z, cp, -0.5f);
    float cosr = fmaf(z, cp, 1.0f);
    float res = (iq & 1) ? sinr : cosr;
    if ((iq + 1) & 2) res = -res;
    return res;
}

__device__ __forceinline__ uint32_t smem_u32(const void* p) {
    uint32_t a;
    asm("{ .reg .u64 t; cvta.to.shared.u64 t, %1; cvt.u32.u64 %0, t; }" : "=r"(a) : "l"(p));
    return a;
}

#define MBAR_INIT(addr, cnt) \
    asm volatile("mbarrier.init.shared.b64 [%0], %1;" :: "r"(addr), "r"(cnt) : "memory")

#define MBAR_WAIT(addr, par) do {                                               \
    uint32_t _m = (addr); uint32_t _p = (par); uint32_t _d;                     \
    asm volatile("{\n\t.reg .pred p;\n\t"                                       \
        "mbarrier.try_wait.parity.acquire.cta.shared::cta.b64 p, [%1], %2;\n\t" \
        "selp.b32 %0, 1, 0, p;\n\t}"                                            \
        : "=r"(_d) : "r"(_m), "r"(_p) : "memory");                              \
    if (!_d) {                                                                  \
        asm volatile("{\n\t.reg .pred P1;\n\t"                                  \
            "WL_%=:\n\t"                                                        \
            "mbarrier.try_wait.parity.acquire.cta.shared::cta.b64 P1, [%0], %1, 0x989680;\n\t" \
            "@P1 bra.uni WD_%=;\n\t"                                            \
            "bra.uni WL_%=;\n\t"                                                \
            "WD_%=:\n\t}" :: "r"(_m), "r"(_p) : "memory");                      \
    }                                                                           \
} while (0)

__device__ __forceinline__ void cp_async16(uint32_t dst, const void* src) {
    asm volatile("cp.async.cg.shared.global [%0], [%1], 16;" :: "r"(dst), "l"(src) : "memory");
}

__device__ __forceinline__ uint64_t make_desc_sw128(uint32_t addr) {
    const uint64_t base = (uint64_t(2) << 61) | (uint64_t(1) << 46) |
                          (uint64_t(64) << 32) | (uint64_t(1) << 16);
    return base | ((uint64_t)(addr >> 4) & 0x3FFF);
}

#if HAS_TCGEN05
__device__ __forceinline__ void mma_tf32_ss(uint32_t d_tmem, uint64_t a_desc,
                                            uint64_t b_desc, uint32_t idesc,
                                            uint32_t enable) {
    asm volatile(
        "{\n\t.reg .pred p;\n\t"
        "setp.ne.u32 p, %4, 0;\n\t"
        "tcgen05.mma.cta_group::1.kind::tf32 [%0], %1, %2, %3, p;\n\t}"
        :: "r"(d_tmem), "l"(a_desc), "l"(b_desc), "r"(idesc), "r"(enable)
        : "memory");
}
#endif

// ---------------------------------------------------------------------------
// Stage 0: round W to tf32 (rna rounding so MMA's tf32 truncation is exact)
// ---------------------------------------------------------------------------
__global__ __launch_bounds__(256) void roundw_kernel(const float* __restrict__ W) {
    int i = (blockIdx.x * 256 + threadIdx.x) * 4;
    float4 v = *(const float4*)(W + i);
    v.x = to_tf32(v.x); v.y = to_tf32(v.y); v.z = to_tf32(v.z); v.w = to_tf32(v.w);
    *(float4*)(g_W32 + i) = v;
}

// ---------------------------------------------------------------------------
// Stage 1: A_perm = tf32(cos(x + theta)), head-transposed layout
// ---------------------------------------------------------------------------
__global__ __launch_bounds__(256) void stage1_kernel(const float* __restrict__ x,
                                                     const float* __restrict__ theta) {
    int gid = blockIdx.x * blockDim.x + threadIdx.x;
    int e0 = gid << 2;
    int b   = e0 >> 22;
    int rem = e0 & (SE_DIM - 1);
    int s   = rem >> 9;
    int e   = rem & (E_DIM - 1);
    int h   = e >> 3;
    int kk  = e & 7;

    float4 xv = *(const float4*)(x + e0);
    float t0 = __ldg(theta + kk + 0);
    float t1 = __ldg(theta + kk + 1);
    float t2 = __ldg(theta + kk + 2);
    float t3 = __ldg(theta + kk + 3);

    float4 o;
    o.x = to_tf32(fast_cos(xv.x + t0));
    o.y = to_tf32(fast_cos(xv.y + t1));
    o.z = to_tf32(fast_cos(xv.z + t2));
    o.w = to_tf32(fast_cos(xv.w + t3));

    size_t off = ((size_t)b << 22) + (size_t)h * (S_DIM * 8) + (size_t)s * 8 + kk;
    *(float4*)(g_A + off) = o;
}

// ---------------------------------------------------------------------------
// Stage 2: tcgen05 tf32 GEMM.  C[m,n] = sum_k A[m,k] * W32[n,k]
// Tile 128x128, K-chunk 32 floats (=128B row, one SW128 atom), 4-stage
// cp.async pipeline. Warps 0-3: producers + epilogue. Warp 4: MMA issuer.
// Non-"a" compile pass gets a correct (slow) SIMT fallback — never expected
// to be selected by the driver on GB300.
// ---------------------------------------------------------------------------
#define NS 4
#define KC 32
#define NCHUNK (K_DIM / KC)              // 16
#define TILE_HALF 16384                  // bytes: 128 rows x 128B
#define STAGE_BYTES (2 * TILE_HALF)      // A + B per stage
#define SMEM_STAGE0 1024
#define GEMM_SMEM (SMEM_STAGE0 + NS * STAGE_BYTES)   // 132096

static constexpr uint32_t IDESC_TF32 =
    (1u << 4)            // D = F32
    | (2u << 7)          // A = TF32
    | (2u << 10)         // B = TF32
    | ((128u / 8u) << 17)    // N = 128
    | ((128u / 16u) << 24);  // M = 128

extern "C" __global__ void __launch_bounds__(160, 1)
gemm_tc_kernel(float* __restrict__ C) {
#if HAS_TCGEN05
    extern __shared__ char smem[];
    uint32_t smem_base = smem_u32(smem);
    int tid = threadIdx.x;
    int wid = tid >> 5;
    int lid = tid & 31;

    uint32_t full_bar = smem_base + 16;   // 4 x 8B
    uint32_t done_bar = smem_base + 64;   // 4 x 8B
    int m0 = blockIdx.y << 7;
    int n0 = blockIdx.x << 7;

    if (tid == 0) {
        for (int s = 0; s < NS; s++) {
            MBAR_INIT(full_bar + 8 * s, 128);  // 128 producer threads arrive
            MBAR_INIT(done_bar + 8 * s, 1);    // tcgen05.commit arrives
        }
    }
    if (wid == 4) {
        asm volatile("tcgen05.alloc.cta_group::1.sync.aligned.shared::cta.b32 [%0], %1;"
                     :: "r"(smem_base), "r"(128u) : "memory");
        asm volatile("tcgen05.relinquish_alloc_permit.cta_group::1.sync.aligned;");
    }
    __syncthreads();
    uint32_t tmem;
    asm volatile("ld.shared.b32 %0, [%1];" : "=r"(tmem) : "r"(smem_base));

    if (wid < 4) {
        // ---- producer: 128 threads, 16 cp.async (8 A + 8 B) per chunk ----
        int row_base = tid >> 3;   // 0..15
        int seg = tid & 7;         // 16B unit within 128B row
        const float* Asrc = g_A   + (size_t)(m0 + row_base) * K_DIM + seg * 4;
        const float* Bsrc = g_W32 + (size_t)(n0 + row_base) * K_DIM + seg * 4;
        // swizzled dst offset; (row&7) constant across j since rows step by 16
        uint32_t dstA0 = SMEM_STAGE0 + row_base * 128 +
                         ((seg * 16) ^ ((row_base & 7) * 16));
        uint32_t dstB0 = dstA0 + TILE_HALF;

        for (int i = 0; i < NCHUNK; i++) {
            int st = i & 3, r = i >> 2;
            if (i >= NS) MBAR_WAIT(done_bar + 8 * st, (r - 1) & 1);
            const float* a = Asrc + i * KC;
            const float* b = Bsrc + i * KC;
            uint32_t sA = smem_base + dstA0 + st * STAGE_BYTES;
            uint32_t sB = smem_base + dstB0 + st * STAGE_BYTES;
#pragma unroll
            for (int j = 0; j < 8; j++) {
                cp_async16(sA + j * 2048, a + (size_t)j * 16 * K_DIM);
                cp_async16(sB + j * 2048, b + (size_t)j * 16 * K_DIM);
            }
            asm volatile("cp.async.mbarrier.arrive.noinc.shared::cta.b64 [%0];"
                         :: "r"(full_bar + 8 * st) : "memory");
        }

        // ---- epilogue: wait last MMA commit (covers all prior MMAs) ----
        MBAR_WAIT(done_bar + 8 * ((NCHUNK - 1) & 3), ((NCHUNK - 1) >> 2) & 1);
        asm volatile("tcgen05.fence::after_thread_sync;" ::: "memory");

        float* Crow = C + (size_t)(m0 + (wid << 5) + lid) * N_DIM + n0;
#pragma unroll
        for (int c = 0; c < 4; c++) {
            uint32_t d[32];
            asm volatile(
                "tcgen05.ld.sync.aligned.32x32b.x32.b32 "
                "{%0, %1, %2, %3, %4, %5, %6, %7, "
                " %8, %9, %10, %11, %12, %13, %14, %15, "
                " %16, %17, %18, %19, %20, %21, %22, %23, "
                " %24, %25, %26, %27, %28, %29, %30, %31}, [%32];"
                : "=r"(d[0]), "=r"(d[1]), "=r"(d[2]), "=r"(d[3]),
                  "=r"(d[4]), "=r"(d[5]), "=r"(d[6]), "=r"(d[7]),
                  "=r"(d[8]), "=r"(d[9]), "=r"(d[10]), "=r"(d[11]),
                  "=r"(d[12]), "=r"(d[13]), "=r"(d[14]), "=r"(d[15]),
                  "=r"(d[16]), "=r"(d[17]), "=r"(d[18]), "=r"(d[19]),
                  "=r"(d[20]), "=r"(d[21]), "=r"(d[22]), "=r"(d[23]),
                  "=r"(d[24]), "=r"(d[25]), "=r"(d[26]), "=r"(d[27]),
                  "=r"(d[28]), "=r"(d[29]), "=r"(d[30]), "=r"(d[31])
                : "r"(tmem + 32 * c));
            asm volatile("tcgen05.wait::ld.sync.aligned;" ::: "memory");
#pragma unroll
            for (int j = 0; j < 8; j++) {
                float4 v = make_float4(__uint_as_float(d[4 * j + 0]),
                                       __uint_as_float(d[4 * j + 1]),
                                       __uint_as_float(d[4 * j + 2]),
                                       __uint_as_float(d[4 * j + 3]));
                *(float4*)(Crow + 32 * c + 4 * j) = v;
            }
        }
        asm volatile("tcgen05.fence::before_thread_sync;" ::: "memory");
    } else {
        // ---- MMA warp ----
        for (int i = 0; i < NCHUNK; i++) {
            int st = i & 3, r = i >> 2;
            MBAR_WAIT(full_bar + 8 * st, r & 1);
            asm volatile("fence.proxy.async.shared::cta;" ::: "memory");
            if (lid == 0) {
                uint32_t abase = smem_base + SMEM_STAGE0 + st * STAGE_BYTES;
                uint64_t ad = make_desc_sw128(abase);
                uint64_t bd = make_desc_sw128(abase + TILE_HALF);
#pragma unroll
                for (int k = 0; k < 4; k++) {
                    mma_tf32_ss(tmem, ad + 2 * k, bd + 2 * k, IDESC_TF32,
                                (i | k) != 0);
                }
                asm volatile(
                    "tcgen05.commit.cta_group::1.mbarrier::arrive::one.shared::cluster.b64 [%0];"
                    :: "r"(done_bar + 8 * st) : "memory");
            }
        }
    }

    __syncthreads();
    if (wid == 4) {
        asm volatile("tcgen05.dealloc.cta_group::1.sync.aligned.b32 %0, %1;"
                     :: "r"(tmem), "r"(128u));
    }
#else
    // Correct SIMT fallback for the non-arch-specific cubin. Never expected
    // to be selected on GB300 (driver prefers the sm_103a image).
    int m0 = blockIdx.y << 7;
    int n0 = blockIdx.x << 7;
    for (int idx = threadIdx.x; idx < 128 * 128; idx += 160) {
        int i = idx >> 7, j = idx & 127;
        const float* a = g_A   + (size_t)(m0 + i) * K_DIM;
        const float* w = g_W32 + (size_t)(n0 + j) * K_DIM;
        float acc = 0.0f;
        for (int k = 0; k < K_DIM; k++) acc = fmaf(a[k], w[k], acc);
        C[(size_t)(m0 + i) * N_DIM + n0 + j] = acc;
    }
#endif
}

// ---------------------------------------------------------------------------
extern "C" void kernel_launch(void* const* d_in, const int* in_sizes, int n_in,
                              void* d_out, int out_size) {
    const float* x     = (const float*)d_in[0];
    const float* theta = (const float*)d_in[1];
    const float* W     = (const float*)d_in[2];
    float* y = (float*)d_out;

    static bool attr_done = false;
    if (!attr_done) {
        cudaFuncSetAttribute(gemm_tc_kernel,
                             cudaFuncAttributeMaxDynamicSharedMemorySize, GEMM_SMEM);
        attr_done = true;
    }

    roundw_kernel<<<N_DIM * K_DIM / (256 * 4), 256>>>(W);
    stage1_kernel<<<32768, 256>>>(x, theta);
    gemm_tc_kernel<<<dim3(N_DIM / 128, M_TOTAL / 128), 160, GEMM_SMEM>>>(y);
}

// round 4
// speedup vs baseline: 6.0520x; 1.1911x over previous
#include <cuda_runtime.h>
#include <cstdint>

#define S_DIM 8192
#define E_DIM 512
#define B_DIM 8
#define SE_DIM (S_DIM * E_DIM)          // 4194304
#define M_TOTAL 65536
#define K_DIM 512
#define N_DIM 512

// tcgen05 is only legal in the arch-specific ("a") compile pass.
#if defined(__CUDA_ARCH_FEAT_SM103_ALL) || defined(__CUDA_ARCH_FEAT_SM100_ALL) || \
    defined(__CUDA_ARCH_FEAT_SM101_ALL) || defined(__CUDA_ARCH_FEAT_SM110_ALL)
#define HAS_TCGEN05 1
#else
#define HAS_TCGEN05 0
#endif

// tf32-rounded W (1MB). No A scratch anymore — A is generated in SMEM.
__device__ float g_W32[(size_t)N_DIM * K_DIM];

// ---------------------------------------------------------------------------
// helpers
// ---------------------------------------------------------------------------
__device__ __forceinline__ float to_tf32(float v) {
    float r;
    asm("cvt.rna.tf32.f32 %0, %1;" : "=f"(r) : "f"(v));
    return r;
}

__device__ __forceinline__ float fast_cos(float t) {
    float q = rintf(t * 0.63661977236758134f);
    int iq = (int)q;
    float r = fmaf(q, -1.57079637050628662109375f, t);
    r = fmaf(q, 4.37113900018624283e-8f, r);
    float z = r * r;
    float sp = fmaf(z, -1.9515295891e-4f, 8.3321608736e-3f);
    sp = fmaf(z, sp, -1.6666654611e-1f);
    float sinr = fmaf(r * z, sp, r);
    float cp = fmaf(z, 2.443315711809948e-5f, -1.388731625493765e-3f);
    cp = fmaf(z, cp, 4.166664568298827e-2f);
    cp = fmaf(z, cp, -0.5f);
    float cosr = fmaf(z, cp, 1.0f);
    float res = (iq & 1) ? sinr : cosr;
    if ((iq + 1) & 2) res = -res;
    return res;
}

__device__ __forceinline__ uint32_t smem_u32(const void* p) {
    uint32_t a;
    asm("{ .reg .u64 t; cvta.to.shared.u64 t, %1; cvt.u32.u64 %0, t; }" : "=r"(a) : "l"(p));
    return a;
}

#define MBAR_INIT(addr, cnt) \
    asm volatile("mbarrier.init.shared.b64 [%0], %1;" :: "r"(addr), "r"(cnt) : "memory")

#define MBAR_WAIT(addr, par) do {                                               \
    uint32_t _m = (addr); uint32_t _p = (par); uint32_t _d;                     \
    asm volatile("{\n\t.reg .pred p;\n\t"                                       \
        "mbarrier.try_wait.parity.acquire.cta.shared::cta.b64 p, [%1], %2;\n\t" \
        "selp.b32 %0, 1, 0, p;\n\t}"                                            \
        : "=r"(_d) : "r"(_m), "r"(_p) : "memory");                              \
    if (!_d) {                                                                  \
        asm volatile("{\n\t.reg .pred P1;\n\t"                                  \
            "WL_%=:\n\t"                                                        \
            "mbarrier.try_wait.parity.acquire.cta.shared::cta.b64 P1, [%0], %1, 0x989680;\n\t" \
            "@P1 bra.uni WD_%=;\n\t"                                            \
            "bra.uni WL_%=;\n\t"                                                \
            "WD_%=:\n\t}" :: "r"(_m), "r"(_p) : "memory");                      \
    }                                                                           \
} while (0)

__device__ __forceinline__ void cp_async16(uint32_t dst, const void* src) {
    asm volatile("cp.async.cg.shared.global [%0], [%1], 16;" :: "r"(dst), "l"(src) : "memory");
}

__device__ __forceinline__ uint64_t make_desc_sw128(uint32_t addr) {
    const uint64_t base = (uint64_t(2) << 61) | (uint64_t(1) << 46) |
                          (uint64_t(64) << 32) | (uint64_t(1) << 16);
    return base | ((uint64_t)(addr >> 4) & 0x3FFF);
}

#define STS128(addr, a0, a1, a2, a3) \
    asm volatile("st.shared.v4.b32 [%0], {%1, %2, %3, %4};" \
                 :: "r"(addr), "r"(a0), "r"(a1), "r"(a2), "r"(a3) : "memory")

#if HAS_TCGEN05
__device__ __forceinline__ void mma_tf32_ss(uint32_t d_tmem, uint64_t a_desc,
                                            uint64_t b_desc, uint32_t idesc,
                                            uint32_t enable) {
    asm volatile(
        "{\n\t.reg .pred p;\n\t"
        "setp.ne.u32 p, %4, 0;\n\t"
        "tcgen05.mma.cta_group::1.kind::tf32 [%0], %1, %2, %3, p;\n\t}"
        :: "r"(d_tmem), "l"(a_desc), "l"(b_desc), "r"(idesc), "r"(enable)
        : "memory");
}
#endif

// ---------------------------------------------------------------------------
// Stage 0: round W to tf32 (rna rounding so MMA's tf32 truncation is exact)
// ---------------------------------------------------------------------------
__global__ __launch_bounds__(256) void roundw_kernel(const float* __restrict__ W) {
    int i = (blockIdx.x * 256 + threadIdx.x) * 4;
    float4 v = *(const float4*)(W + i);
    v.x = to_tf32(v.x); v.y = to_tf32(v.y); v.z = to_tf32(v.z); v.w = to_tf32(v.w);
    *(float4*)(g_W32 + i) = v;
}

// ---------------------------------------------------------------------------
// Fused kernel: one CTA = one 128-row output tile (full N=512 width).
// Tile t: b = t>>6, h = t&63, rows m = t*128 + r.
//   A[r][k] = tf32(cos(x[b, r*64 + k/8, h*8 + k%8] + theta[k%8]))
//   C[m][n] = sum_k A[r][k] * W32[n][k]
// x is read exactly once chip-wide; no gmem A scratch.
// 8 worker warps (A gen + B cp.async + epilogue), 1 MMA warp. NS=2 stages.
// ---------------------------------------------------------------------------
#define NCHUNK 16                        // K chunks of 32 floats
#define SMEM_A0 1024
#define A_STAGE 16384                    // 128 rows x 128B
#define SMEM_B0 (SMEM_A0 + 2 * A_STAGE)  // 33792
#define B_STAGE 65536                    // 512 rows x 128B
#define FUSED_SMEM (SMEM_B0 + 2 * B_STAGE)   // 164864

static constexpr uint32_t IDESC_N256 =
    (1u << 4)                // D = F32
    | (2u << 7)              // A = TF32
    | (2u << 10)             // B = TF32
    | ((256u / 8u) << 17)    // N = 256
    | ((128u / 16u) << 24);  // M = 128

extern "C" __global__ void __launch_bounds__(288, 1)
fused_kernel(const float* __restrict__ x, const float* __restrict__ theta,
             float* __restrict__ C) {
#if HAS_TCGEN05
    extern __shared__ char smem[];
    uint32_t smem_base = smem_u32(smem);
    int tid = threadIdx.x;
    int wid = tid >> 5;
    int lid = tid & 31;

    int t = blockIdx.x;
    int b = t >> 6;
    int h = t & 63;
    int m0 = t << 7;

    uint32_t full_bar = smem_base + 16;   // 2 x 8B, count 512
    uint32_t done_bar = smem_base + 48;   // 2 x 8B, count 1

    if (tid == 0) {
        for (int s = 0; s < 2; s++) {
            MBAR_INIT(full_bar + 8 * s, 512);   // 256 noinc + 256 explicit
            MBAR_INIT(done_bar + 8 * s, 1);
        }
    }
    if (wid == 8) {
        asm volatile("tcgen05.alloc.cta_group::1.sync.aligned.shared::cta.b32 [%0], %1;"
                     :: "r"(smem_base), "r"(512u) : "memory");
        asm volatile("tcgen05.relinquish_alloc_permit.cta_group::1.sync.aligned;");
    }
    __syncthreads();
    uint32_t tmem;
    asm volatile("ld.shared.b32 %0, [%1];" : "=r"(tmem) : "r"(smem_base));

    if (wid < 8) {
        // ================= worker warps =================
        // A-gen mapping: r = tid>>1 (0..127), half = tid&1
        int r = tid >> 1;
        int half = tid & 1;
        const float* xs = x + ((size_t)b << 22) + (size_t)h * 8;
        float th0 = __ldg(theta + 0), th1 = __ldg(theta + 1);
        float th2 = __ldg(theta + 2), th3 = __ldg(theta + 3);
        float th4 = __ldg(theta + 4), th5 = __ldg(theta + 5);
        float th6 = __ldg(theta + 6), th7 = __ldg(theta + 7);
        int xa = (r & 7) * 16;                    // swizzle XOR for A row
        uint32_t arow = smem_base + SMEM_A0 + r * 128;

        // B mapping: rb = tid>>3 (0..31), seg = tid&7; 16 rows per thread (stride 32)
        int rb = tid >> 3;
        int seg = tid & 7;
        const float* bsrc0 = g_W32 + (size_t)rb * K_DIM + seg * 4;
        uint32_t bdst0 = smem_base + SMEM_B0 + rb * 128 + ((seg * 16) ^ ((rb & 7) * 16));

        for (int i = 0; i < NCHUNK; i++) {
            int st = i & 1;
            if (i >= 2) MBAR_WAIT(done_bar + 8 * st, ((i - 2) >> 1) & 1);

            // ---- B: 16 cp.async of 16B (rows rb, rb+32, ..., rb+480) ----
            const float* bs = bsrc0 + i * 32;
            uint32_t bd = bdst0 + st * B_STAGE;
#pragma unroll
            for (int j = 0; j < 16; j++)
                cp_async16(bd + j * 32 * 128, bs + (size_t)j * 32 * K_DIM);

            // ---- A: 16 cos values (2 s-rows x 8 wires) ----
            int sb = r * 64 + i * 4 + half * 2;
            const float* xp = xs + (size_t)sb * E_DIM;
            float4 x0 = *(const float4*)(xp);
            float4 x1 = *(const float4*)(xp + 4);
            float4 x2 = *(const float4*)(xp + E_DIM);
            float4 x3 = *(const float4*)(xp + E_DIM + 4);

            uint32_t v[16];
            v[0]  = __float_as_uint(to_tf32(fast_cos(x0.x + th0)));
            v[1]  = __float_as_uint(to_tf32(fast_cos(x0.y + th1)));
            v[2]  = __float_as_uint(to_tf32(fast_cos(x0.z + th2)));
            v[3]  = __float_as_uint(to_tf32(fast_cos(x0.w + th3)));
            v[4]  = __float_as_uint(to_tf32(fast_cos(x1.x + th4)));
            v[5]  = __float_as_uint(to_tf32(fast_cos(x1.y + th5)));
            v[6]  = __float_as_uint(to_tf32(fast_cos(x1.z + th6)));
            v[7]  = __float_as_uint(to_tf32(fast_cos(x1.w + th7)));
            v[8]  = __float_as_uint(to_tf32(fast_cos(x2.x + th0)));
            v[9]  = __float_as_uint(to_tf32(fast_cos(x2.y + th1)));
            v[10] = __float_as_uint(to_tf32(fast_cos(x2.z + th2)));
            v[11] = __float_as_uint(to_tf32(fast_cos(x2.w + th3)));
            v[12] = __float_as_uint(to_tf32(fast_cos(x3.x + th4)));
            v[13] = __float_as_uint(to_tf32(fast_cos(x3.y + th5)));
            v[14] = __float_as_uint(to_tf32(fast_cos(x3.z + th6)));
            v[15] = __float_as_uint(to_tf32(fast_cos(x3.w + th7)));

            uint32_t ad = arow + st * A_STAGE;
            STS128(ad + ((half * 64 + 0)  ^ xa), v[0],  v[1],  v[2],  v[3]);
            STS128(ad + ((half * 64 + 16) ^ xa), v[4],  v[5],  v[6],  v[7]);
            STS128(ad + ((half * 64 + 32) ^ xa), v[8],  v[9],  v[10], v[11]);
            STS128(ad + ((half * 64 + 48) ^ xa), v[12], v[13], v[14], v[15]);

            asm volatile("fence.proxy.async.shared::cta;" ::: "memory");
            asm volatile("mbarrier.arrive.shared.b64 _, [%0];"
                         :: "r"(full_bar + 8 * st) : "memory");
            asm volatile("cp.async.mbarrier.arrive.noinc.shared::cta.b64 [%0];"
                         :: "r"(full_bar + 8 * st) : "memory");
        }

        // ================= epilogue =================
        MBAR_WAIT(done_bar + 8 * ((NCHUNK - 1) & 1), ((NCHUNK - 1) >> 1) & 1);
        asm volatile("tcgen05.fence::after_thread_sync;" ::: "memory");

        int row = (wid & 3) * 32 + lid;
        int c0 = (wid >= 4) ? 256 : 0;
        float* Crow = C + (size_t)(m0 + row) * N_DIM + c0;
#pragma unroll
        for (int c = 0; c < 8; c++) {
            uint32_t d[32];
            asm volatile(
                "tcgen05.ld.sync.aligned.32x32b.x32.b32 "
                "{%0, %1, %2, %3, %4, %5, %6, %7, "
                " %8, %9, %10, %11, %12, %13, %14, %15, "
                " %16, %17, %18, %19, %20, %21, %22, %23, "
                " %24, %25, %26, %27, %28, %29, %30, %31}, [%32];"
                : "=r"(d[0]), "=r"(d[1]), "=r"(d[2]), "=r"(d[3]),
                  "=r"(d[4]), "=r"(d[5]), "=r"(d[6]), "=r"(d[7]),
                  "=r"(d[8]), "=r"(d[9]), "=r"(d[10]), "=r"(d[11]),
                  "=r"(d[12]), "=r"(d[13]), "=r"(d[14]), "=r"(d[15]),
                  "=r"(d[16]), "=r"(d[17]), "=r"(d[18]), "=r"(d[19]),
                  "=r"(d[20]), "=r"(d[21]), "=r"(d[22]), "=r"(d[23]),
                  "=r"(d[24]), "=r"(d[25]), "=r"(d[26]), "=r"(d[27]),
                  "=r"(d[28]), "=r"(d[29]), "=r"(d[30]), "=r"(d[31])
                : "r"(tmem + c0 + 32 * c));
            asm volatile("tcgen05.wait::ld.sync.aligned;" ::: "memory");
#pragma unroll
            for (int j = 0; j < 8; j++) {
                float4 o = make_float4(__uint_as_float(d[4 * j + 0]),
                                       __uint_as_float(d[4 * j + 1]),
                                       __uint_as_float(d[4 * j + 2]),
                                       __uint_as_float(d[4 * j + 3]));
                *(float4*)(Crow + 32 * c + 4 * j) = o;
            }
        }
        asm volatile("tcgen05.fence::before_thread_sync;" ::: "memory");
    } else {
        // ================= MMA warp =================
        for (int i = 0; i < NCHUNK; i++) {
            int st = i & 1;
            MBAR_WAIT(full_bar + 8 * st, (i >> 1) & 1);
            asm volatile("fence.proxy.async.shared::cta;" ::: "memory");
            if (lid == 0) {
                uint32_t ab = smem_base + SMEM_A0 + st * A_STAGE;
                uint32_t bb = smem_base + SMEM_B0 + st * B_STAGE;
                uint64_t ad  = make_desc_sw128(ab);
                uint64_t bd0 = make_desc_sw128(bb);
                uint64_t bd1 = make_desc_sw128(bb + 256 * 128);
#pragma unroll
                for (int k = 0; k < 4; k++) {
                    uint32_t en = (i | k) != 0;
                    mma_tf32_ss(tmem,       ad + 2 * k, bd0 + 2 * k, IDESC_N256, en);
                    mma_tf32_ss(tmem + 256, ad + 2 * k, bd1 + 2 * k, IDESC_N256, en);
                }
                asm volatile(
                    "tcgen05.commit.cta_group::1.mbarrier::arrive::one.shared::cluster.b64 [%0];"
                    :: "r"(done_bar + 8 * st) : "memory");
            }
        }
    }

    __syncthreads();
    if (wid == 8) {
        asm volatile("tcgen05.dealloc.cta_group::1.sync.aligned.b32 %0, %1;"
                     :: "r"(tmem), "r"(512u));
    }
#else
    // Correct SIMT fallback for the non-arch-specific cubin (never selected
    // on GB300; driver prefers the sm_103a image).
    int t = blockIdx.x;
    int b = t >> 6;
    int h = t & 63;
    int m0 = t << 7;
    for (int idx = threadIdx.x; idx < 128 * N_DIM; idx += 288) {
        int r = idx >> 9, n = idx & 511;
        float acc = 0.0f;
        for (int k = 0; k < K_DIM; k++) {
            int s = r * 64 + (k >> 3);
            int wire = k & 7;
            float a = fast_cos(x[(size_t)b * SE_DIM + (size_t)s * E_DIM + h * 8 + wire]
                               + theta[wire]);
            acc = fmaf(to_tf32(a), g_W32[(size_t)n * K_DIM + k], acc);
        }
        C[(size_t)(m0 + r) * N_DIM + n] = acc;
    }
#endif
}

// ---------------------------------------------------------------------------
extern "C" void kernel_launch(void* const* d_in, const int* in_sizes, int n_in,
                              void* d_out, int out_size) {
    const float* x     = (const float*)d_in[0];
    const float* theta = (const float*)d_in[1];
    const float* W     = (const float*)d_in[2];
    float* y = (float*)d_out;

    static bool attr_done = false;
    if (!attr_done) {
        cudaFuncSetAttribute(fused_kernel,
                             cudaFuncAttributeMaxDynamicSharedMemorySize, FUSED_SMEM);
        attr_done = true;
    }

    roundw_kernel<<<N_DIM * K_DIM / (256 * 4), 256>>>(W);
    fused_kernel<<<512, 288, FUSED_SMEM>>>(x, theta, y);
}